// round 13
// baseline (speedup 1.0000x reference)
#include <cuda_runtime.h>

#define BN 1024
#define CN 128
#define DN 16
#define SN 4
#define K3N 23
#define K2N 5
#define K1N 2
#define ON 4

// Stream layout per (e,c), consumed in exactly this order:
//   for i in 0..15:  [S1: 4 floats]
//     for j in i..15:  [S2: 4 floats]
//       for h in (j>>1)..7:  [8 floats: (o0l0,o0l1,o1l0,o1l1,o2l0,o2l1,o3l0,o3l1)]
// total floats = 16*4 + 136*4 + 444*8 = 4160
#define STREAMF 4160
#define NSLOTS  596   // 16 S1 + 136 S2 + 444 h-slots

#define FCH 4         // final channel chunks
#define FCW 32        // channels per chunk
#define NBF 4         // nodes per final_part block

// ---------------- static device scratch ----------------
__device__ float g_stream[(size_t)SN * CN * STREAMF];   // 8.5 MB
__device__ float g_y[(size_t)BN * CN * ON];
__device__ int   g_bucket[SN * BN];
__device__ int   g_cnt[SN];
__device__ int   g_sched[16];
__device__ int   g_nsched;

// ---------------- symmetrized-u helpers ----------------
__device__ __forceinline__ float u3val(int o, int i, int j, int l, int k,
                                       const float* __restrict__ u3_0,
                                       const float* __restrict__ u3_1) {
    return (o == 0) ? u3_0[((i * 16 + j) * 16 + l) * K3N + k]
                    : u3_1[((((o - 1) * 16 + i) * 16 + j) * 16 + l) * K3N + k];
}
// orbit sum over distinct permutations of sorted triple a<=b<=g
__device__ __forceinline__ float orbit3(int o, int a, int b, int g, int k,
                                        const float* __restrict__ A,
                                        const float* __restrict__ B) {
    if (a == b && b == g) return u3val(o, a, a, a, k, A, B);
    if (a == b) return u3val(o, a, a, g, k, A, B) + u3val(o, a, g, a, k, A, B) + u3val(o, g, a, a, k, A, B);
    if (b == g) return u3val(o, a, b, b, k, A, B) + u3val(o, b, a, b, k, A, B) + u3val(o, b, b, a, k, A, B);
    return u3val(o, a, b, g, k, A, B) + u3val(o, a, g, b, k, A, B) + u3val(o, b, a, g, k, A, B)
         + u3val(o, b, g, a, k, A, B) + u3val(o, g, a, b, k, A, B) + u3val(o, g, b, a, k, A, B);
}
__device__ __forceinline__ float u2val(int o, int i, int j, int k,
                                       const float* __restrict__ u2_0,
                                       const float* __restrict__ u2_1) {
    return (o == 0) ? u2_0[(i * 16 + j) * K2N + k]
                    : u2_1[(((o - 1) * 16 + i) * 16 + j) * K2N + k];
}

// ---------------- kernel 1: build coefficient stream (+ bucket in block 0) ----------------
// grid = 4 species * 596 slots; 128 threads = channel c.
__global__ void sbuild_kernel(const float* __restrict__ u3_0, const float* __restrict__ u3_1,
                              const float* __restrict__ u2_0, const float* __restrict__ u2_1,
                              const float* __restrict__ u1_0, const float* __restrict__ u1_1,
                              const float* __restrict__ w3,   const float* __restrict__ w2,
                              const float* __restrict__ w1,   const int* __restrict__ sp) {
    __shared__ int scnt[SN];

    // block 0 additionally buckets nodes by species + builds 128-node chunk schedule
    if (blockIdx.x == 0) {
        int t = threadIdx.x;
        if (t < SN) scnt[t] = 0;
        __syncthreads();
#pragma unroll
        for (int m = 0; m < BN / 128; m++) {
            int node = t + m * 128;
            int e2 = sp[node];
            int pos = atomicAdd(&scnt[e2], 1);
            g_bucket[e2 * BN + pos] = node;
        }
        __syncthreads();
        if (t < SN) g_cnt[t] = scnt[t];
        if (t == 0) {
            int n = 0;
            for (int e2 = 0; e2 < SN; e2++)
                for (int s2 = 0; s2 < scnt[e2]; s2 += 128)
                    g_sched[n++] = (e2 << 16) | s2;
            g_nsched = n;
        }
    }

    int e = blockIdx.x / NSLOTS;
    int slot = blockIdx.x % NSLOTS;
    int c = threadIdx.x;

    // locate this slot in the canonical stream order (thread 0 only, broadcast)
    __shared__ int sinfo[5];
    if (threadIdx.x == 0) {
        int s = slot, type = -1, I = 0, J = 0, H = 0, mypos = 0, pos = 0;
        for (int i = 0; i < 16 && type < 0; i++) {
            if (s == 0) { type = 0; I = i; mypos = pos; break; }
            s--; pos += 4;
            for (int j = i; j < 16; j++) {
                if (s == 0) { type = 1; I = i; J = j; mypos = pos; break; }
                s--; pos += 4;
                int nh = 8 - (j >> 1);
                if (s < nh) { type = 2; I = i; J = j; H = (j >> 1) + s; mypos = pos + s * 8; break; }
                s -= nh; pos += nh * 8;
            }
        }
        sinfo[0] = type; sinfo[1] = I; sinfo[2] = J; sinfo[3] = H; sinfo[4] = mypos;
    }
    __syncthreads();
    int type = sinfo[0], I = sinfo[1], J = sinfo[2], H = sinfo[3], mypos = sinfo[4];
    size_t base = (size_t)(e * CN + c) * STREAMF + mypos;

    if (type == 0) {            // S1: uw1[o,I]
#pragma unroll
        for (int o = 0; o < 4; o++) {
            int tt = (o > 0);
            float acc = 0.f;
#pragma unroll
            for (int k = 0; k < K1N; k++) {
                float uu = (o == 0) ? u1_0[I * K1N + k] : u1_1[((o - 1) * 16 + I) * K1N + k];
                acc = fmaf(uu, w1[((tt * SN + e) * K1N + k) * CN + c], acc);
            }
            g_stream[base + o] = acc;
        }
    } else if (type == 1) {     // S2: orbit-symmetrized uw2 for pair (I<=J)
#pragma unroll
        for (int o = 0; o < 4; o++) {
            int tt = (o > 0);
            float acc = 0.f;
#pragma unroll
            for (int k = 0; k < K2N; k++) {
                float uu = u2val(o, I, J, k, u2_0, u2_1);
                if (I < J) uu += u2val(o, J, I, k, u2_0, u2_1);
                acc = fmaf(uu, w2[((tt * SN + e) * K2N + k) * CN + c], acc);
            }
            g_stream[base + o] = acc;
        }
    } else {                    // h-slot: 8 values (4 o x 2 l), orbit-symmetrized uw3
        __shared__ float us[K3N][8];
        for (int v = threadIdx.x; v < K3N * 8; v += 128) {
            int k = v >> 3, q = v & 7;
            int o = q >> 1, dl = q & 1, l = 2 * H + dl;
            float val = 0.f;
            if (l >= J) val = orbit3(o, I, J, l, k, u3_0, u3_1);
            us[k][q] = val;
        }
        __syncthreads();
        float w3r0[K3N], w3r1[K3N];
#pragma unroll
        for (int k = 0; k < K3N; k++) {
            w3r0[k] = w3[((0 * SN + e) * K3N + k) * CN + c];
            w3r1[k] = w3[((1 * SN + e) * K3N + k) * CN + c];
        }
        float acc[8] = {0, 0, 0, 0, 0, 0, 0, 0};
#pragma unroll
        for (int k = 0; k < K3N; k++) {
            float4 a = *(const float4*)&us[k][0];
            float4 b = *(const float4*)&us[k][4];
            acc[0] = fmaf(a.x, w3r0[k], acc[0]);
            acc[1] = fmaf(a.y, w3r0[k], acc[1]);
            acc[2] = fmaf(a.z, w3r1[k], acc[2]);
            acc[3] = fmaf(a.w, w3r1[k], acc[3]);
            acc[4] = fmaf(b.x, w3r1[k], acc[4]);
            acc[5] = fmaf(b.y, w3r1[k], acc[5]);
            acc[6] = fmaf(b.z, w3r1[k], acc[6]);
            acc[7] = fmaf(b.w, w3r1[k], acc[7]);
        }
#pragma unroll
        for (int q = 0; q < 8; q++) g_stream[base + q] = acc[q];
    }
}

// ---------------- kernel 2: main contraction (1 node/thread) ----------------
// One thread per (node, channel). Block = (c, 128-node chunk of one species).
__global__ void __launch_bounds__(128, 4) main_kernel(const float* __restrict__ x) {
    __shared__ float4 st4[STREAMF / 4];
    int bx = blockIdx.x;
    int c = bx & 127;
    int chunk = bx >> 7;
    if (chunk >= g_nsched) return;
    int si = g_sched[chunk];
    int e = si >> 16, start = si & 0xffff;

    // stage this (e,c) coefficient stream into smem (coalesced)
    const float4* src = (const float4*)(g_stream + (size_t)(e * CN + c) * STREAMF);
    for (int p = threadIdx.x; p < STREAMF / 4; p += 128) st4[p] = src[p];

    int cnt = g_cnt[e];
    int idx = start + threadIdx.x;
    bool active = idx < cnt;
    int b = active ? g_bucket[e * BN + idx] : 0;

    float xv[16];
    {
        float4 z = make_float4(0.f, 0.f, 0.f, 0.f);
        float4 xr[4] = {z, z, z, z};
        if (active) {
            const float4* xp = (const float4*)(x + ((size_t)b * CN + c) * 16);
            xr[0] = xp[0]; xr[1] = xp[1]; xr[2] = xp[2]; xr[3] = xp[3];
        }
        *(float4*)&xv[0]  = xr[0];
        *(float4*)&xv[4]  = xr[1];
        *(float4*)&xv[8]  = xr[2];
        *(float4*)&xv[12] = xr[3];
    }
    unsigned long long Xp[8];
#pragma unroll
    for (int h = 0; h < 8; h++)
        asm("mov.b64 %0, {%1, %2};" : "=l"(Xp[h]) : "f"(xv[2 * h]), "f"(xv[2 * h + 1]));

    __syncthreads();
    const float* sp = (const float*)st4;

    unsigned long long acc3[4] = {0ull, 0ull, 0ull, 0ull};  // packed (even-l, odd-l) sums per o
    float accs[4] = {0.f, 0.f, 0.f, 0.f};

#pragma unroll
    for (int i = 0; i < 16; i++) {
        float4 s1 = *(const float4*)sp; sp += 4;
        accs[0] = fmaf(s1.x, xv[i], accs[0]);
        accs[1] = fmaf(s1.y, xv[i], accs[1]);
        accs[2] = fmaf(s1.z, xv[i], accs[2]);
        accs[3] = fmaf(s1.w, xv[i], accs[3]);
#pragma unroll
        for (int j = i; j < 16; j++) {
            float p = xv[i] * xv[j];
            float4 s2 = *(const float4*)sp; sp += 4;
            accs[0] = fmaf(s2.x, p, accs[0]);
            accs[1] = fmaf(s2.y, p, accs[1]);
            accs[2] = fmaf(s2.z, p, accs[2]);
            accs[3] = fmaf(s2.w, p, accs[3]);
            unsigned long long p2;
            asm("mov.b64 %0, {%1, %1};" : "=l"(p2) : "f"(p));
#pragma unroll
            for (int h = (j >> 1); h < 8; h++) {
                unsigned long long m2;
                asm("mul.rn.f32x2 %0, %1, %2;" : "=l"(m2) : "l"(p2), "l"(Xp[h]));
                ulonglong2 qa = *(const ulonglong2*)sp;
                ulonglong2 qb = *(const ulonglong2*)(sp + 4);
                sp += 8;
                asm("fma.rn.f32x2 %0, %1, %2, %0;" : "+l"(acc3[0]) : "l"(qa.x), "l"(m2));
                asm("fma.rn.f32x2 %0, %1, %2, %0;" : "+l"(acc3[1]) : "l"(qa.y), "l"(m2));
                asm("fma.rn.f32x2 %0, %1, %2, %0;" : "+l"(acc3[2]) : "l"(qb.x), "l"(m2));
                asm("fma.rn.f32x2 %0, %1, %2, %0;" : "+l"(acc3[3]) : "l"(qb.y), "l"(m2));
            }
        }
    }

    if (active) {
        float out[4];
#pragma unroll
        for (int o = 0; o < 4; o++) {
            float lo, hi;
            asm("mov.b64 {%0, %1}, %2;" : "=f"(lo), "=f"(hi) : "l"(acc3[o]));
            out[o] = accs[o] + lo + hi;
        }
        *(float4*)(g_y + ((size_t)b * CN + c) * ON) = *(float4*)out;
    }
}

// ---------------- kernel 3: equivariant linear, c-split + direct atomic output ----------------
// grid = 1024 = (256 node-groups of 4 x 4 channel-chunks); block = 256 threads.
// Scale folded into the contribution; chunks accumulate straight into d_out via
// REDG.ADD (no partial planes, no reduce kernel). d_out pre-zeroed by memset.
__global__ void __launch_bounds__(256) final_part(const float* __restrict__ w_lin,
                                                  float* __restrict__ out) {
    __shared__ float ysm[FCW][4][NBF];   // [ci][oo][nn], 2 KB
    int nodeblk = blockIdx.x >> 2;
    int chunk = blockIdx.x & 3;
    int b0 = nodeblk * NBF;
    int c0 = chunk * FCW;
    int tid = threadIdx.x;

    // stage y slice: 4 nodes x 32 channels x 4 oo = 128 float4 (coalesced)
    if (tid < NBF * FCW) {
        int nn = tid >> 5;
        int ci = tid & 31;
        float4 v = *(const float4*)(g_y + (size_t)(b0 + nn) * 512 + (size_t)(c0 + ci) * 4);
        ysm[ci][0][nn] = v.x;
        ysm[ci][1][nn] = v.y;
        ysm[ci][2][nn] = v.z;
        ysm[ci][3][nn] = v.w;
    }
    __syncthreads();

    int f0 = tid * 2;
    int oo = f0 >> 7;            // 0..3, warp-uniform
    int n0 = f0 & 127;           // even
    int tsel = (oo > 0) ? 1 : 0;
    const float* wbase = w_lin + (size_t)tsel * CN * CN + (size_t)c0 * CN + n0;

    unsigned long long accA[2] = {0ull, 0ull};  // output n0,  node pairs (0,1),(2,3)
    unsigned long long accB[2] = {0ull, 0ull};  // output n0+1
#pragma unroll
    for (int ci = 0; ci < FCW; ci++) {
        float2 wv = *(const float2*)(wbase + ci * 128);
        unsigned long long w0p, w1p;
        asm("mov.b64 %0, {%1, %1};" : "=l"(w0p) : "f"(wv.x));
        asm("mov.b64 %0, {%1, %1};" : "=l"(w1p) : "f"(wv.y));
        ulonglong2 Y0 = *(const ulonglong2*)&ysm[ci][oo][0];  // nodes 0..3 packed (bcast)
        asm("fma.rn.f32x2 %0, %1, %2, %0;" : "+l"(accA[0]) : "l"(w0p), "l"(Y0.x));
        asm("fma.rn.f32x2 %0, %1, %2, %0;" : "+l"(accA[1]) : "l"(w0p), "l"(Y0.y));
        asm("fma.rn.f32x2 %0, %1, %2, %0;" : "+l"(accB[0]) : "l"(w1p), "l"(Y0.x));
        asm("fma.rn.f32x2 %0, %1, %2, %0;" : "+l"(accB[1]) : "l"(w1p), "l"(Y0.y));
    }

    const float scale = 0.08838834764831845f; // 1/sqrt(128)
    int s0 = (oo == 0) ? n0 : (128 + n0 * 3 + (oo - 1));
    int s1 = (oo == 0) ? (n0 + 1) : (128 + (n0 + 1) * 3 + (oo - 1));
#pragma unroll
    for (int p = 0; p < 2; p++) {
        float a0, a1, b0v, b1v;
        asm("mov.b64 {%0, %1}, %2;" : "=f"(a0), "=f"(a1) : "l"(accA[p]));
        asm("mov.b64 {%0, %1}, %2;" : "=f"(b0v), "=f"(b1v) : "l"(accB[p]));
        atomicAdd(&out[(size_t)(b0 + 2 * p) * 512 + s0],     a0 * scale);
        atomicAdd(&out[(size_t)(b0 + 2 * p + 1) * 512 + s0], a1 * scale);
        atomicAdd(&out[(size_t)(b0 + 2 * p) * 512 + s1],     b0v * scale);
        atomicAdd(&out[(size_t)(b0 + 2 * p + 1) * 512 + s1], b1v * scale);
    }
}

// ---------------- launch ----------------
extern "C" void kernel_launch(void* const* d_in, const int* in_sizes, int n_in,
                              void* d_out, int out_size) {
    const float* x    = (const float*)d_in[0];
    const float* u3_0 = (const float*)d_in[1];
    const float* u3_1 = (const float*)d_in[2];
    const float* u2_0 = (const float*)d_in[3];
    const float* u2_1 = (const float*)d_in[4];
    const float* u1_0 = (const float*)d_in[5];
    const float* u1_1 = (const float*)d_in[6];
    const float* w3   = (const float*)d_in[7];
    const float* w2   = (const float*)d_in[8];
    const float* w1   = (const float*)d_in[9];
    const float* wlin = (const float*)d_in[10];
    const int*   sp   = (const int*)d_in[11];

    cudaMemsetAsync(d_out, 0, (size_t)out_size * sizeof(float));
    sbuild_kernel<<<SN * NSLOTS, 128>>>(u3_0, u3_1, u2_0, u2_1, u1_0, u1_1, w3, w2, w1, sp);
    main_kernel<<<128 * 11, 128>>>(x);      // 11 = hard bound on 128-node chunks
    final_part<<<(BN / NBF) * FCH, 256>>>(wlin, (float*)d_out);
}

// round 14
// speedup vs baseline: 1.0210x; 1.0210x over previous
#include <cuda_runtime.h>

#define BN 1024
#define CN 128
#define DN 16
#define SN 4
#define K3N 23
#define K2N 5
#define K1N 2
#define ON 4

// Stream layout per (e,c), consumed in exactly this order:
//   for i in 0..15:  [S1: 4 floats]
//     for j in i..15:  [S2: 4 floats]
//       for h in (j>>1)..7:  [8 floats: (o0l0,o0l1,o1l0,o1l1,o2l0,o2l1,o3l0,o3l1)]
// total floats = 16*4 + 136*4 + 444*8 = 4160
#define STREAMF 4160
#define NSLOTS  596   // 16 S1 + 136 S2 + 444 h-slots

#define FCH 4         // final channel chunks
#define FCW 32        // channels per chunk
#define NBF 4         // nodes per final_part block

// ---------------- static device scratch ----------------
__device__ float g_stream[(size_t)SN * CN * STREAMF];   // 8.5 MB
__device__ float g_y[(size_t)BN * CN * ON];
__device__ float g_part[(size_t)FCH * BN * 512];        // 8.4 MB partials
__device__ int   g_bucket[SN * BN];
__device__ int   g_cnt[SN];
__device__ int   g_sched[16];
__device__ int   g_nsched;

// ---------------- symmetrized-u helpers ----------------
__device__ __forceinline__ float u3val(int o, int i, int j, int l, int k,
                                       const float* __restrict__ u3_0,
                                       const float* __restrict__ u3_1) {
    return (o == 0) ? u3_0[((i * 16 + j) * 16 + l) * K3N + k]
                    : u3_1[((((o - 1) * 16 + i) * 16 + j) * 16 + l) * K3N + k];
}
// orbit sum over distinct permutations of sorted triple a<=b<=g
__device__ __forceinline__ float orbit3(int o, int a, int b, int g, int k,
                                        const float* __restrict__ A,
                                        const float* __restrict__ B) {
    if (a == b && b == g) return u3val(o, a, a, a, k, A, B);
    if (a == b) return u3val(o, a, a, g, k, A, B) + u3val(o, a, g, a, k, A, B) + u3val(o, g, a, a, k, A, B);
    if (b == g) return u3val(o, a, b, b, k, A, B) + u3val(o, b, a, b, k, A, B) + u3val(o, b, b, a, k, A, B);
    return u3val(o, a, b, g, k, A, B) + u3val(o, a, g, b, k, A, B) + u3val(o, b, a, g, k, A, B)
         + u3val(o, b, g, a, k, A, B) + u3val(o, g, a, b, k, A, B) + u3val(o, g, b, a, k, A, B);
}
__device__ __forceinline__ float u2val(int o, int i, int j, int k,
                                       const float* __restrict__ u2_0,
                                       const float* __restrict__ u2_1) {
    return (o == 0) ? u2_0[(i * 16 + j) * K2N + k]
                    : u2_1[(((o - 1) * 16 + i) * 16 + j) * K2N + k];
}

// ---------------- kernel 1: build coefficient stream, ALL species per block ----------------
// grid = 596 slots; 128 threads = channel c. The e-independent symmetrized-u
// gather (the scattered, L2-bound part) is computed ONCE per slot, then the
// cheap coalesced w-loads + FMAs loop over the 4 species.
__global__ void sbuild_kernel(const float* __restrict__ u3_0, const float* __restrict__ u3_1,
                              const float* __restrict__ u2_0, const float* __restrict__ u2_1,
                              const float* __restrict__ u1_0, const float* __restrict__ u1_1,
                              const float* __restrict__ w3,   const float* __restrict__ w2,
                              const float* __restrict__ w1,   const int* __restrict__ sp) {
    __shared__ int scnt[SN];

    // block 0 additionally buckets nodes by species + builds 128-node chunk schedule
    if (blockIdx.x == 0) {
        int t = threadIdx.x;
        if (t < SN) scnt[t] = 0;
        __syncthreads();
#pragma unroll
        for (int m = 0; m < BN / 128; m++) {
            int node = t + m * 128;
            int e2 = sp[node];
            int pos = atomicAdd(&scnt[e2], 1);
            g_bucket[e2 * BN + pos] = node;
        }
        __syncthreads();
        if (t < SN) g_cnt[t] = scnt[t];
        if (t == 0) {
            int n = 0;
            for (int e2 = 0; e2 < SN; e2++)
                for (int s2 = 0; s2 < scnt[e2]; s2 += 128)
                    g_sched[n++] = (e2 << 16) | s2;
            g_nsched = n;
        }
    }

    int slot = blockIdx.x;
    int c = threadIdx.x;

    // locate this slot in the canonical stream order (thread 0 only, broadcast)
    __shared__ int sinfo[5];
    if (threadIdx.x == 0) {
        int s = slot, type = -1, I = 0, J = 0, H = 0, mypos = 0, pos = 0;
        for (int i = 0; i < 16 && type < 0; i++) {
            if (s == 0) { type = 0; I = i; mypos = pos; break; }
            s--; pos += 4;
            for (int j = i; j < 16; j++) {
                if (s == 0) { type = 1; I = i; J = j; mypos = pos; break; }
                s--; pos += 4;
                int nh = 8 - (j >> 1);
                if (s < nh) { type = 2; I = i; J = j; H = (j >> 1) + s; mypos = pos + s * 8; break; }
                s -= nh; pos += nh * 8;
            }
        }
        sinfo[0] = type; sinfo[1] = I; sinfo[2] = J; sinfo[3] = H; sinfo[4] = mypos;
    }
    __syncthreads();
    int type = sinfo[0], I = sinfo[1], J = sinfo[2], H = sinfo[3], mypos = sinfo[4];

    if (type == 0) {            // S1: uw1[o,I] for all species
        float uu[4][K1N];
#pragma unroll
        for (int o = 0; o < 4; o++)
#pragma unroll
            for (int k = 0; k < K1N; k++)
                uu[o][k] = (o == 0) ? u1_0[I * K1N + k] : u1_1[((o - 1) * 16 + I) * K1N + k];
#pragma unroll
        for (int e = 0; e < SN; e++) {
            size_t base = (size_t)(e * CN + c) * STREAMF + mypos;
#pragma unroll
            for (int o = 0; o < 4; o++) {
                int tt = (o > 0);
                float acc = 0.f;
#pragma unroll
                for (int k = 0; k < K1N; k++)
                    acc = fmaf(uu[o][k], w1[((tt * SN + e) * K1N + k) * CN + c], acc);
                g_stream[base + o] = acc;
            }
        }
    } else if (type == 1) {     // S2: orbit-symmetrized uw2 for pair (I<=J), all species
        float uu[4][K2N];
#pragma unroll
        for (int o = 0; o < 4; o++)
#pragma unroll
            for (int k = 0; k < K2N; k++) {
                float v = u2val(o, I, J, k, u2_0, u2_1);
                if (I < J) v += u2val(o, J, I, k, u2_0, u2_1);
                uu[o][k] = v;
            }
#pragma unroll
        for (int e = 0; e < SN; e++) {
            size_t base = (size_t)(e * CN + c) * STREAMF + mypos;
#pragma unroll
            for (int o = 0; o < 4; o++) {
                int tt = (o > 0);
                float acc = 0.f;
#pragma unroll
                for (int k = 0; k < K2N; k++)
                    acc = fmaf(uu[o][k], w2[((tt * SN + e) * K2N + k) * CN + c], acc);
                g_stream[base + o] = acc;
            }
        }
    } else {                    // h-slot: symmetrized uw3 gathered ONCE, used 4x
        __shared__ float us[K3N][8];
        for (int v = threadIdx.x; v < K3N * 8; v += 128) {
            int k = v >> 3, q = v & 7;
            int o = q >> 1, dl = q & 1, l = 2 * H + dl;
            float val = 0.f;
            if (l >= J) val = orbit3(o, I, J, l, k, u3_0, u3_1);
            us[k][q] = val;
        }
        __syncthreads();

#pragma unroll
        for (int e = 0; e < SN; e++) {
            float w3r0[K3N], w3r1[K3N];
#pragma unroll
            for (int k = 0; k < K3N; k++) {
                w3r0[k] = w3[((0 * SN + e) * K3N + k) * CN + c];
                w3r1[k] = w3[((1 * SN + e) * K3N + k) * CN + c];
            }
            float acc[8] = {0, 0, 0, 0, 0, 0, 0, 0};
#pragma unroll
            for (int k = 0; k < K3N; k++) {
                float4 a = *(const float4*)&us[k][0];
                float4 b = *(const float4*)&us[k][4];
                acc[0] = fmaf(a.x, w3r0[k], acc[0]);
                acc[1] = fmaf(a.y, w3r0[k], acc[1]);
                acc[2] = fmaf(a.z, w3r1[k], acc[2]);
                acc[3] = fmaf(a.w, w3r1[k], acc[3]);
                acc[4] = fmaf(b.x, w3r1[k], acc[4]);
                acc[5] = fmaf(b.y, w3r1[k], acc[5]);
                acc[6] = fmaf(b.z, w3r1[k], acc[6]);
                acc[7] = fmaf(b.w, w3r1[k], acc[7]);
            }
            size_t base = (size_t)(e * CN + c) * STREAMF + mypos;
#pragma unroll
            for (int q = 0; q < 8; q++) g_stream[base + q] = acc[q];
        }
    }
}

// ---------------- kernel 2: main contraction (1 node/thread) ----------------
// One thread per (node, channel). Block = (c, 128-node chunk of one species).
__global__ void __launch_bounds__(128, 4) main_kernel(const float* __restrict__ x) {
    __shared__ float4 st4[STREAMF / 4];
    int bx = blockIdx.x;
    int c = bx & 127;
    int chunk = bx >> 7;
    if (chunk >= g_nsched) return;
    int si = g_sched[chunk];
    int e = si >> 16, start = si & 0xffff;

    // stage this (e,c) coefficient stream into smem (coalesced)
    const float4* src = (const float4*)(g_stream + (size_t)(e * CN + c) * STREAMF);
    for (int p = threadIdx.x; p < STREAMF / 4; p += 128) st4[p] = src[p];

    int cnt = g_cnt[e];
    int idx = start + threadIdx.x;
    bool active = idx < cnt;
    int b = active ? g_bucket[e * BN + idx] : 0;

    float xv[16];
    {
        float4 z = make_float4(0.f, 0.f, 0.f, 0.f);
        float4 xr[4] = {z, z, z, z};
        if (active) {
            const float4* xp = (const float4*)(x + ((size_t)b * CN + c) * 16);
            xr[0] = xp[0]; xr[1] = xp[1]; xr[2] = xp[2]; xr[3] = xp[3];
        }
        *(float4*)&xv[0]  = xr[0];
        *(float4*)&xv[4]  = xr[1];
        *(float4*)&xv[8]  = xr[2];
        *(float4*)&xv[12] = xr[3];
    }
    unsigned long long Xp[8];
#pragma unroll
    for (int h = 0; h < 8; h++)
        asm("mov.b64 %0, {%1, %2};" : "=l"(Xp[h]) : "f"(xv[2 * h]), "f"(xv[2 * h + 1]));

    __syncthreads();
    const float* sp = (const float*)st4;

    unsigned long long acc3[4] = {0ull, 0ull, 0ull, 0ull};  // packed (even-l, odd-l) sums per o
    float accs[4] = {0.f, 0.f, 0.f, 0.f};

#pragma unroll
    for (int i = 0; i < 16; i++) {
        float4 s1 = *(const float4*)sp; sp += 4;
        accs[0] = fmaf(s1.x, xv[i], accs[0]);
        accs[1] = fmaf(s1.y, xv[i], accs[1]);
        accs[2] = fmaf(s1.z, xv[i], accs[2]);
        accs[3] = fmaf(s1.w, xv[i], accs[3]);
#pragma unroll
        for (int j = i; j < 16; j++) {
            float p = xv[i] * xv[j];
            float4 s2 = *(const float4*)sp; sp += 4;
            accs[0] = fmaf(s2.x, p, accs[0]);
            accs[1] = fmaf(s2.y, p, accs[1]);
            accs[2] = fmaf(s2.z, p, accs[2]);
            accs[3] = fmaf(s2.w, p, accs[3]);
            unsigned long long p2;
            asm("mov.b64 %0, {%1, %1};" : "=l"(p2) : "f"(p));
#pragma unroll
            for (int h = (j >> 1); h < 8; h++) {
                unsigned long long m2;
                asm("mul.rn.f32x2 %0, %1, %2;" : "=l"(m2) : "l"(p2), "l"(Xp[h]));
                ulonglong2 qa = *(const ulonglong2*)sp;
                ulonglong2 qb = *(const ulonglong2*)(sp + 4);
                sp += 8;
                asm("fma.rn.f32x2 %0, %1, %2, %0;" : "+l"(acc3[0]) : "l"(qa.x), "l"(m2));
                asm("fma.rn.f32x2 %0, %1, %2, %0;" : "+l"(acc3[1]) : "l"(qa.y), "l"(m2));
                asm("fma.rn.f32x2 %0, %1, %2, %0;" : "+l"(acc3[2]) : "l"(qb.x), "l"(m2));
                asm("fma.rn.f32x2 %0, %1, %2, %0;" : "+l"(acc3[3]) : "l"(qb.y), "l"(m2));
            }
        }
    }

    if (active) {
        float out[4];
#pragma unroll
        for (int o = 0; o < 4; o++) {
            float lo, hi;
            asm("mov.b64 {%0, %1}, %2;" : "=f"(lo), "=f"(hi) : "l"(acc3[o]));
            out[o] = accs[o] + lo + hi;
        }
        *(float4*)(g_y + ((size_t)b * CN + c) * ON) = *(float4*)out;
    }
}

// ---------------- kernel 3a: equivariant linear, c-split partials ----------------
// grid = 1024 = (256 node-groups of 4 x 4 channel-chunks); block = 256 threads.
// Per-thread w MLP = 32 (full 32-channel chunk, fully unrolled LDG.64s).
__global__ void __launch_bounds__(256) final_part(const float* __restrict__ w_lin) {
    __shared__ float ysm[FCW][4][NBF];   // [ci][oo][nn], 2 KB
    int nodeblk = blockIdx.x >> 2;
    int chunk = blockIdx.x & 3;
    int b0 = nodeblk * NBF;
    int c0 = chunk * FCW;
    int tid = threadIdx.x;

    // stage y slice: 4 nodes x 32 channels x 4 oo = 128 float4 (coalesced)
    if (tid < NBF * FCW) {
        int nn = tid >> 5;
        int ci = tid & 31;
        float4 v = *(const float4*)(g_y + (size_t)(b0 + nn) * 512 + (size_t)(c0 + ci) * 4);
        ysm[ci][0][nn] = v.x;
        ysm[ci][1][nn] = v.y;
        ysm[ci][2][nn] = v.z;
        ysm[ci][3][nn] = v.w;
    }
    __syncthreads();

    int f0 = tid * 2;
    int oo = f0 >> 7;            // 0..3, warp-uniform
    int n0 = f0 & 127;           // even
    int tsel = (oo > 0) ? 1 : 0;
    const float* wbase = w_lin + (size_t)tsel * CN * CN + (size_t)c0 * CN + n0;

    unsigned long long accA[2] = {0ull, 0ull};  // output n0,  node pairs (0,1),(2,3)
    unsigned long long accB[2] = {0ull, 0ull};  // output n0+1
#pragma unroll
    for (int ci = 0; ci < FCW; ci++) {
        float2 wv = *(const float2*)(wbase + ci * 128);
        unsigned long long w0p, w1p;
        asm("mov.b64 %0, {%1, %1};" : "=l"(w0p) : "f"(wv.x));
        asm("mov.b64 %0, {%1, %1};" : "=l"(w1p) : "f"(wv.y));
        ulonglong2 Y0 = *(const ulonglong2*)&ysm[ci][oo][0];  // nodes 0..3 packed (bcast)
        asm("fma.rn.f32x2 %0, %1, %2, %0;" : "+l"(accA[0]) : "l"(w0p), "l"(Y0.x));
        asm("fma.rn.f32x2 %0, %1, %2, %0;" : "+l"(accA[1]) : "l"(w0p), "l"(Y0.y));
        asm("fma.rn.f32x2 %0, %1, %2, %0;" : "+l"(accB[0]) : "l"(w1p), "l"(Y0.x));
        asm("fma.rn.f32x2 %0, %1, %2, %0;" : "+l"(accB[1]) : "l"(w1p), "l"(Y0.y));
    }

    int s0 = (oo == 0) ? n0 : (128 + n0 * 3 + (oo - 1));
    int s1 = (oo == 0) ? (n0 + 1) : (128 + (n0 + 1) * 3 + (oo - 1));
    float* pb = g_part + (size_t)chunk * (BN * 512);
#pragma unroll
    for (int p = 0; p < 2; p++) {
        float a0, a1, b0v, b1v;
        asm("mov.b64 {%0, %1}, %2;" : "=f"(a0), "=f"(a1) : "l"(accA[p]));
        asm("mov.b64 {%0, %1}, %2;" : "=f"(b0v), "=f"(b1v) : "l"(accB[p]));
        pb[(size_t)(b0 + 2 * p) * 512 + s0]     = a0;
        pb[(size_t)(b0 + 2 * p + 1) * 512 + s0] = a1;
        pb[(size_t)(b0 + 2 * p) * 512 + s1]     = b0v;
        pb[(size_t)(b0 + 2 * p + 1) * 512 + s1] = b1v;
    }
}

// ---------------- kernel 3b: reduce 4 partials + scale ----------------
__global__ void final_reduce(float* __restrict__ out) {
    const int PLANE = BN * 512 / 4;     // float4s per plane = 131072
    int t = blockIdx.x * 256 + threadIdx.x;
    const float4* p = (const float4*)g_part;
    float4 a = p[t], b = p[t + PLANE], c = p[t + 2 * PLANE], d = p[t + 3 * PLANE];
    const float scale = 0.08838834764831845f; // 1/sqrt(128)
    float4 r;
    r.x = (a.x + b.x + c.x + d.x) * scale;
    r.y = (a.y + b.y + c.y + d.y) * scale;
    r.z = (a.z + b.z + c.z + d.z) * scale;
    r.w = (a.w + b.w + c.w + d.w) * scale;
    ((float4*)out)[t] = r;
}

// ---------------- launch ----------------
extern "C" void kernel_launch(void* const* d_in, const int* in_sizes, int n_in,
                              void* d_out, int out_size) {
    const float* x    = (const float*)d_in[0];
    const float* u3_0 = (const float*)d_in[1];
    const float* u3_1 = (const float*)d_in[2];
    const float* u2_0 = (const float*)d_in[3];
    const float* u2_1 = (const float*)d_in[4];
    const float* u1_0 = (const float*)d_in[5];
    const float* u1_1 = (const float*)d_in[6];
    const float* w3   = (const float*)d_in[7];
    const float* w2   = (const float*)d_in[8];
    const float* w1   = (const float*)d_in[9];
    const float* wlin = (const float*)d_in[10];
    const int*   sp   = (const int*)d_in[11];

    sbuild_kernel<<<NSLOTS, 128>>>(u3_0, u3_1, u2_0, u2_1, u1_0, u1_1, w3, w2, w1, sp);
    main_kernel<<<128 * 11, 128>>>(x);      // 11 = hard bound on 128-node chunks
    final_part<<<(BN / NBF) * FCH, 256>>>(wlin);
    final_reduce<<<BN * 512 / 4 / 256, 256>>>((float*)d_out);
}